// round 2
// baseline (speedup 1.0000x reference)
#include <cuda_runtime.h>
#include <math.h>

// Problem constants
#define BSZ     4
#define SEQ     1024
#define HIDDEN  1024
#define NHEADS  16
#define HDIM    64
#define MTOT    (BSZ*SEQ)          // 4096
#define NBH     (BSZ*NHEADS)       // 64

// Scratch (device globals; allocation is forbidden)
__device__ float g_q[MTOT * HIDDEN];
__device__ float g_k[MTOT * HIDDEN];
__device__ float g_v[MTOT * HIDDEN];
__device__ float g_o[MTOT * HIDDEN];

// ---------------------------------------------------------------------------
// SGEMM: C[M,N] = A[M,K] * W[N,K]^T   (M=4096, N=K=1024)
// 128x128 block tile, BK=8, 256 threads, 8x8 per-thread microtile.
// ---------------------------------------------------------------------------
__device__ __forceinline__ void sgemm_body(const float* __restrict__ A,
                                           const float* __restrict__ W,
                                           float* __restrict__ C) {
    const int K = HIDDEN;
    const int N = HIDDEN;

    __shared__ float As[8][128];
    __shared__ float Ws[8][128];

    const int tid  = threadIdx.x;
    const int lRow = tid >> 1;          // 0..127
    const int lCol = (tid & 1) << 2;    // 0 or 4

    const float* Ap = A + ((size_t)(blockIdx.y * 128 + lRow)) * K + lCol;
    const float* Wp = W + ((size_t)(blockIdx.x * 128 + lRow)) * K + lCol;

    const int ty = tid >> 4;            // 0..15
    const int tx = tid & 15;            // 0..15

    float acc[8][8];
#pragma unroll
    for (int i = 0; i < 8; i++)
#pragma unroll
        for (int j = 0; j < 8; j++) acc[i][j] = 0.f;

    for (int k0 = 0; k0 < K; k0 += 8) {
        float4 a4 = *(const float4*)(Ap + k0);
        float4 w4 = *(const float4*)(Wp + k0);
        __syncthreads();
        As[lCol + 0][lRow] = a4.x;
        As[lCol + 1][lRow] = a4.y;
        As[lCol + 2][lRow] = a4.z;
        As[lCol + 3][lRow] = a4.w;
        Ws[lCol + 0][lRow] = w4.x;
        Ws[lCol + 1][lRow] = w4.y;
        Ws[lCol + 2][lRow] = w4.z;
        Ws[lCol + 3][lRow] = w4.w;
        __syncthreads();

#pragma unroll
        for (int kk = 0; kk < 8; kk++) {
            float ar[8], wr[8];
            *(float4*)(ar)     = *(const float4*)&As[kk][ty * 8];
            *(float4*)(ar + 4) = *(const float4*)&As[kk][ty * 8 + 4];
            *(float4*)(wr)     = *(const float4*)&Ws[kk][tx * 8];
            *(float4*)(wr + 4) = *(const float4*)&Ws[kk][tx * 8 + 4];
#pragma unroll
            for (int i = 0; i < 8; i++)
#pragma unroll
                for (int j = 0; j < 8; j++)
                    acc[i][j] = fmaf(ar[i], wr[j], acc[i][j]);
        }
    }

    float* Cp = C + ((size_t)(blockIdx.y * 128 + ty * 8)) * N + blockIdx.x * 128 + tx * 8;
#pragma unroll
    for (int i = 0; i < 8; i++) {
        *(float4*)(Cp + (size_t)i * N)     = make_float4(acc[i][0], acc[i][1], acc[i][2], acc[i][3]);
        *(float4*)(Cp + (size_t)i * N + 4) = make_float4(acc[i][4], acc[i][5], acc[i][6], acc[i][7]);
    }
}

__global__ __launch_bounds__(256) void qkv_gemm_kernel(const float* __restrict__ x,
                                                       const float* __restrict__ wq,
                                                       const float* __restrict__ wk,
                                                       const float* __restrict__ wv) {
    const float* W = (blockIdx.z == 0) ? wq : (blockIdx.z == 1) ? wk : wv;
    float* C       = (blockIdx.z == 0) ? g_q : (blockIdx.z == 1) ? g_k : g_v;
    sgemm_body(x, W, C);
}

__global__ __launch_bounds__(256) void out_gemm_kernel(const float* __restrict__ wo,
                                                       float* __restrict__ out) {
    sgemm_body(g_o, wo, out);
}

// ---------------------------------------------------------------------------
// Flash attention over contiguous (1024 x 64) per-(b,h) chunks.
// grid: (qtiles=8, bh=64); 128 threads; one query row per thread.
// ---------------------------------------------------------------------------
__global__ __launch_bounds__(128) void attn_kernel() {
    __shared__ float Ks[64 * 64];
    __shared__ float Vs[64 * 64];

    const int bh = blockIdx.y;
    const int qi = blockIdx.x * 128 + threadIdx.x;   // query row within head
    const size_t base = (size_t)bh * (SEQ * HDIM);

    const float* Qh = g_q + base;
    const float* Kh = g_k + base;
    const float* Vh = g_v + base;

    // Load q row, pre-scaled by HEAD_DIM^-0.5 = 0.125 (exact power of two)
    float q[64];
#pragma unroll
    for (int d4 = 0; d4 < 16; d4++) {
        float4 t = *(const float4*)(Qh + (size_t)qi * HDIM + d4 * 4);
        q[d4 * 4 + 0] = t.x * 0.125f;
        q[d4 * 4 + 1] = t.y * 0.125f;
        q[d4 * 4 + 2] = t.z * 0.125f;
        q[d4 * 4 + 3] = t.w * 0.125f;
    }

    float o[64];
#pragma unroll
    for (int d = 0; d < 64; d++) o[d] = 0.f;
    float m = -1e30f, l = 0.f;

    for (int t = 0; t < SEQ / 64; t++) {
        const float4* Kg = (const float4*)(Kh + (size_t)t * 64 * HDIM);
        const float4* Vg = (const float4*)(Vh + (size_t)t * 64 * HDIM);
        float4* Ks4 = (float4*)Ks;
        float4* Vs4 = (float4*)Vs;
        __syncthreads();
#pragma unroll
        for (int i = 0; i < 8; i++) {
            Ks4[threadIdx.x + i * 128] = Kg[threadIdx.x + i * 128];
            Vs4[threadIdx.x + i * 128] = Vg[threadIdx.x + i * 128];
        }
        __syncthreads();

        for (int g = 0; g < 4; g++) {           // groups of 16 keys
            float s[16];
#pragma unroll
            for (int j = 0; j < 16; j++) {
                const float4* krow = (const float4*)(Ks + (g * 16 + j) * HDIM);
                float a0 = 0.f, a1 = 0.f, a2 = 0.f, a3 = 0.f;
#pragma unroll
                for (int d4 = 0; d4 < 16; d4++) {
                    float4 kv = krow[d4];
                    a0 = fmaf(q[d4 * 4 + 0], kv.x, a0);
                    a1 = fmaf(q[d4 * 4 + 1], kv.y, a1);
                    a2 = fmaf(q[d4 * 4 + 2], kv.z, a2);
                    a3 = fmaf(q[d4 * 4 + 3], kv.w, a3);
                }
                s[j] = (a0 + a1) + (a2 + a3);
            }
            float mt = m;
#pragma unroll
            for (int j = 0; j < 16; j++) mt = fmaxf(mt, s[j]);
            float corr = __expf(m - mt);
            m = mt;
            l *= corr;
#pragma unroll
            for (int d = 0; d < 64; d++) o[d] *= corr;
#pragma unroll
            for (int j = 0; j < 16; j++) {
                float p = __expf(s[j] - m);
                l += p;
                const float4* vrow = (const float4*)(Vs + (g * 16 + j) * HDIM);
#pragma unroll
                for (int d4 = 0; d4 < 16; d4++) {
                    float4 vv = vrow[d4];
                    o[d4 * 4 + 0] = fmaf(p, vv.x, o[d4 * 4 + 0]);
                    o[d4 * 4 + 1] = fmaf(p, vv.y, o[d4 * 4 + 1]);
                    o[d4 * 4 + 2] = fmaf(p, vv.z, o[d4 * 4 + 2]);
                    o[d4 * 4 + 3] = fmaf(p, vv.w, o[d4 * 4 + 3]);
                }
            }
        }
    }

    const float inv = 1.f / l;
    float* Oh = g_o + base + (size_t)qi * HDIM;
#pragma unroll
    for (int d4 = 0; d4 < 16; d4++) {
        float4 t;
        t.x = o[d4 * 4 + 0] * inv;
        t.y = o[d4 * 4 + 1] * inv;
        t.z = o[d4 * 4 + 2] * inv;
        t.w = o[d4 * 4 + 3] * inv;
        *(float4*)(Oh + d4 * 4) = t;
    }
}

// ---------------------------------------------------------------------------
extern "C" void kernel_launch(void* const* d_in, const int* in_sizes, int n_in,
                              void* d_out, int out_size) {
    const float* x  = (const float*)d_in[0];
    const float* wq = (const float*)d_in[1];
    const float* wk = (const float*)d_in[2];
    const float* wv = (const float*)d_in[3];
    const float* wo = (const float*)d_in[4];
    float* out = (float*)d_out;

    // QKV projections: grid (N/128, M/128, 3)
    qkv_gemm_kernel<<<dim3(HIDDEN / 128, MTOT / 128, 3), 256>>>(x, wq, wk, wv);

    // Attention: 8 query tiles x 64 (b,h) chunks
    attn_kernel<<<dim3(SEQ / 128, NBH), 128>>>();

    // Output projection
    out_gemm_kernel<<<dim3(HIDDEN / 128, MTOT / 128), 256>>>(wo, out);
}

// round 5
// speedup vs baseline: 1.5120x; 1.5120x over previous
#include <cuda_runtime.h>
#include <cuda_bf16.h>
#include <cstdint>
#include <math.h>

// Problem constants
#define BSZ     4
#define SEQ     1024
#define HIDDEN  1024
#define NHEADS  16
#define HDIM    64
#define MTOT    (BSZ*SEQ)          // 4096
#define NBH     (BSZ*NHEADS)       // 64

// ---------------------------------------------------------------------------
// Scratch (device globals; allocation is forbidden)
// ---------------------------------------------------------------------------
__device__ float g_q[MTOT * HIDDEN];
__device__ float g_k[MTOT * HIDDEN];
__device__ float g_v[MTOT * HIDDEN];
__device__ float g_o[MTOT * HIDDEN];

__device__ __nv_bfloat16 g_xh[MTOT * HIDDEN];
__device__ __nv_bfloat16 g_xl[MTOT * HIDDEN];
__device__ __nv_bfloat16 g_oh[MTOT * HIDDEN];
__device__ __nv_bfloat16 g_ol[MTOT * HIDDEN];
__device__ __nv_bfloat16 g_wqh[HIDDEN * HIDDEN];
__device__ __nv_bfloat16 g_wql[HIDDEN * HIDDEN];
__device__ __nv_bfloat16 g_wkh[HIDDEN * HIDDEN];
__device__ __nv_bfloat16 g_wkl[HIDDEN * HIDDEN];
__device__ __nv_bfloat16 g_wvh[HIDDEN * HIDDEN];
__device__ __nv_bfloat16 g_wvl[HIDDEN * HIDDEN];
__device__ __nv_bfloat16 g_woh[HIDDEN * HIDDEN];
__device__ __nv_bfloat16 g_wol[HIDDEN * HIDDEN];

// ---------------------------------------------------------------------------
// Warp-level tensor helpers (baseline PTX: valid under compute_103)
// ---------------------------------------------------------------------------
__device__ __forceinline__ uint32_t smem_to_u32(const void* p) {
    uint32_t addr;
    asm("{ .reg .u64 t; cvta.to.shared.u64 t, %1; cvt.u32.u64 %0, t; }"
        : "=r"(addr) : "l"(p));
    return addr;
}

__device__ __forceinline__ void ldsm_x4(uint32_t addr, uint32_t* r) {
    asm volatile("ldmatrix.sync.aligned.m8n8.x4.shared.b16 {%0,%1,%2,%3}, [%4];"
        : "=r"(r[0]), "=r"(r[1]), "=r"(r[2]), "=r"(r[3]) : "r"(addr));
}

__device__ __forceinline__ void mma_bf16(float* c, const uint32_t* a,
                                         uint32_t b0, uint32_t b1) {
    asm volatile(
        "mma.sync.aligned.m16n8k16.row.col.f32.bf16.bf16.f32 "
        "{%0,%1,%2,%3}, {%4,%5,%6,%7}, {%8,%9}, {%0,%1,%2,%3};"
        : "+f"(c[0]), "+f"(c[1]), "+f"(c[2]), "+f"(c[3])
        : "r"(a[0]), "r"(a[1]), "r"(a[2]), "r"(a[3]), "r"(b0), "r"(b1));
}

// ---------------------------------------------------------------------------
// fp32 -> bf16 hi/lo split conversion (x = hi + lo, ~16 mantissa bits)
// ---------------------------------------------------------------------------
__global__ __launch_bounds__(256) void convert_split_kernel(
    const float* __restrict__ src,
    __nv_bfloat16* __restrict__ hi,
    __nv_bfloat16* __restrict__ lo, int n4) {
    int i = blockIdx.x * blockDim.x + threadIdx.x;
    if (i >= n4) return;
    float4 v = ((const float4*)src)[i];
    __nv_bfloat16 hx = __float2bfloat16(v.x);
    __nv_bfloat16 hy = __float2bfloat16(v.y);
    __nv_bfloat16 hz = __float2bfloat16(v.z);
    __nv_bfloat16 hw = __float2bfloat16(v.w);
    __nv_bfloat16 lx = __float2bfloat16(v.x - __bfloat162float(hx));
    __nv_bfloat16 ly = __float2bfloat16(v.y - __bfloat162float(hy));
    __nv_bfloat16 lz = __float2bfloat16(v.z - __bfloat162float(hz));
    __nv_bfloat16 lw = __float2bfloat16(v.w - __bfloat162float(hw));
    __nv_bfloat162* hp = (__nv_bfloat162*)hi;
    __nv_bfloat162* lp = (__nv_bfloat162*)lo;
    hp[i * 2 + 0] = __nv_bfloat162(hx, hy);
    hp[i * 2 + 1] = __nv_bfloat162(hz, hw);
    lp[i * 2 + 0] = __nv_bfloat162(lx, ly);
    lp[i * 2 + 1] = __nv_bfloat162(lz, lw);
}

// ---------------------------------------------------------------------------
// mma.sync GEMM: C[4096,1024] = (Ah+Al)[M,K] * (Wh+Wl)[N,K]^T  (both K-major)
// CTA tile 128x128, BK=32, 256 threads (8 warps, warp tile 64x32).
// SMEM rows padded to 80B -> ldmatrix conflict-free (row*5+c mod 8 bijective).
// 3-way bf16 split accumulation: AhBh + AhBl + AlBh.
// ---------------------------------------------------------------------------
#define NCHUNKS  (HIDDEN / 32)     // 32 K-chunks
#define TILE_B   10240             // 128 rows * 80 bytes

__device__ __forceinline__ void gemm_mma_body(
    const __nv_bfloat16* __restrict__ Ah, const __nv_bfloat16* __restrict__ Al,
    const __nv_bfloat16* __restrict__ Wh, const __nv_bfloat16* __restrict__ Wl,
    float* __restrict__ C) {
    __shared__ __align__(16) char sm[4 * TILE_B];   // sAh | sAl | sWh | sWl

    const int tid  = threadIdx.x;
    const int lane = tid & 31;
    const int wid  = tid >> 5;
    const int wm   = (wid >> 2) * 64;   // warp M offset (0/64)
    const int wn   = (wid & 3) * 32;    // warp N offset (0..96)
    const int blockM = blockIdx.y * 128;
    const int blockN = blockIdx.x * 128;
    const uint32_t sbase = smem_to_u32(sm);

    // global prefetch mapping: each thread owns 2 rows x 1 16B-chunk per tile
    const int prow = tid >> 2;          // 0..63
    const int pc   = tid & 3;           // 16B chunk within 64B k-slab
    const uint4* gAh = (const uint4*)Ah;
    const uint4* gAl = (const uint4*)Al;
    const uint4* gWh = (const uint4*)Wh;
    const uint4* gWl = (const uint4*)Wl;
    const size_t gA0 = (size_t)(blockM + prow) * 128 + pc;
    const size_t gA1 = gA0 + (size_t)64 * 128;
    const size_t gW0 = (size_t)(blockN + prow) * 128 + pc;
    const size_t gW1 = gW0 + (size_t)64 * 128;
    const uint32_t s0 = prow * 80 + pc * 16;
    const uint32_t s1 = s0 + 64 * 80;

    // ldmatrix per-lane offsets
    const int r8 = lane & 7, sel = lane >> 3;
    const uint32_t a_lane = (uint32_t)((wm + r8 + (sel & 1) * 8) * 80 + (sel >> 1) * 16);
    const uint32_t b_lane = (uint32_t)((wn + (sel >> 1) * 8 + r8) * 80 + (sel & 1) * 16);

    float acc[4][4][4];
#pragma unroll
    for (int m = 0; m < 4; m++)
#pragma unroll
        for (int n = 0; n < 4; n++)
#pragma unroll
            for (int i = 0; i < 4; i++) acc[m][n][i] = 0.f;

    uint4 pf[8];
    {
        const size_t o = 0;
        pf[0] = gAh[gA0 + o]; pf[1] = gAh[gA1 + o];
        pf[2] = gAl[gA0 + o]; pf[3] = gAl[gA1 + o];
        pf[4] = gWh[gW0 + o]; pf[5] = gWh[gW1 + o];
        pf[6] = gWl[gW0 + o]; pf[7] = gWl[gW1 + o];
    }

    for (int ch = 0; ch < NCHUNKS; ch++) {
        __syncthreads();
        *(uint4*)(sm + 0 * TILE_B + s0) = pf[0];
        *(uint4*)(sm + 0 * TILE_B + s1) = pf[1];
        *(uint4*)(sm + 1 * TILE_B + s0) = pf[2];
        *(uint4*)(sm + 1 * TILE_B + s1) = pf[3];
        *(uint4*)(sm + 2 * TILE_B + s0) = pf[4];
        *(uint4*)(sm + 2 * TILE_B + s1) = pf[5];
        *(uint4*)(sm + 3 * TILE_B + s0) = pf[6];
        *(uint4*)(sm + 3 * TILE_B + s1) = pf[7];
        __syncthreads();

        if (ch + 1 < NCHUNKS) {
            const size_t o = (size_t)(ch + 1) * 4;
            pf[0] = gAh[gA0 + o]; pf[1] = gAh[gA1 + o];
            pf[2] = gAl[gA0 + o]; pf[3] = gAl[gA1 + o];
            pf[4] = gWh[gW0 + o]; pf[5] = gWh[gW1 + o];
            pf[6] = gWl[gW0 + o]; pf[7] = gWl[gW1 + o];
        }

#pragma unroll
        for (int ks = 0; ks < 2; ks++) {
            uint32_t bh[8], bl[8];
            ldsm_x4(sbase + 2 * TILE_B + b_lane + ks * 32, bh);
            ldsm_x4(sbase + 2 * TILE_B + b_lane + 16 * 80 + ks * 32, bh + 4);
            ldsm_x4(sbase + 3 * TILE_B + b_lane + ks * 32, bl);
            ldsm_x4(sbase + 3 * TILE_B + b_lane + 16 * 80 + ks * 32, bl + 4);
#pragma unroll
            for (int m = 0; m < 4; m++) {
                uint32_t ah[4], al[4];
                ldsm_x4(sbase + 0 * TILE_B + a_lane + m * (16 * 80) + ks * 32, ah);
                ldsm_x4(sbase + 1 * TILE_B + a_lane + m * (16 * 80) + ks * 32, al);
#pragma unroll
                for (int n = 0; n < 4; n++) {
                    mma_bf16(acc[m][n], ah, bh[n * 2], bh[n * 2 + 1]);
                    mma_bf16(acc[m][n], ah, bl[n * 2], bl[n * 2 + 1]);
                    mma_bf16(acc[m][n], al, bh[n * 2], bh[n * 2 + 1]);
                }
            }
        }
    }

    // Epilogue: fragment -> fp32 C
    const int cr = lane >> 2;
    const int cc = (lane & 3) * 2;
#pragma unroll
    for (int m = 0; m < 4; m++) {
#pragma unroll
        for (int n = 0; n < 4; n++) {
            const size_t row = (size_t)(blockM + wm + m * 16 + cr);
            const size_t col = (size_t)(blockN + wn + n * 8 + cc);
            *(float2*)(C + row * HIDDEN + col) =
                make_float2(acc[m][n][0], acc[m][n][1]);
            *(float2*)(C + (row + 8) * HIDDEN + col) =
                make_float2(acc[m][n][2], acc[m][n][3]);
        }
    }
}

__global__ __launch_bounds__(256) void qkv_gemm_mma_kernel() {
    const __nv_bfloat16* Wh = (blockIdx.z == 0) ? g_wqh : (blockIdx.z == 1) ? g_wkh : g_wvh;
    const __nv_bfloat16* Wl = (blockIdx.z == 0) ? g_wql : (blockIdx.z == 1) ? g_wkl : g_wvl;
    float* C = (blockIdx.z == 0) ? g_q : (blockIdx.z == 1) ? g_k : g_v;
    gemm_mma_body(g_xh, g_xl, Wh, Wl, C);
}

__global__ __launch_bounds__(256) void out_gemm_mma_kernel(float* __restrict__ out) {
    gemm_mma_body(g_oh, g_ol, g_woh, g_wol, out);
}

// ---------------------------------------------------------------------------
// Flash attention over contiguous (1024 x 64) per-(b,h) chunks (unchanged).
// ---------------------------------------------------------------------------
__global__ __launch_bounds__(128) void attn_kernel() {
    __shared__ float Ks[64 * 64];
    __shared__ float Vs[64 * 64];

    const int bh = blockIdx.y;
    const int qi = blockIdx.x * 128 + threadIdx.x;
    const size_t base = (size_t)bh * (SEQ * HDIM);

    const float* Qh = g_q + base;
    const float* Kh = g_k + base;
    const float* Vh = g_v + base;

    float q[64];
#pragma unroll
    for (int d4 = 0; d4 < 16; d4++) {
        float4 t = *(const float4*)(Qh + (size_t)qi * HDIM + d4 * 4);
        q[d4 * 4 + 0] = t.x * 0.125f;
        q[d4 * 4 + 1] = t.y * 0.125f;
        q[d4 * 4 + 2] = t.z * 0.125f;
        q[d4 * 4 + 3] = t.w * 0.125f;
    }

    float o[64];
#pragma unroll
    for (int d = 0; d < 64; d++) o[d] = 0.f;
    float m = -1e30f, l = 0.f;

    for (int t = 0; t < SEQ / 64; t++) {
        const float4* Kg = (const float4*)(Kh + (size_t)t * 64 * HDIM);
        const float4* Vg = (const float4*)(Vh + (size_t)t * 64 * HDIM);
        float4* Ks4 = (float4*)Ks;
        float4* Vs4 = (float4*)Vs;
        __syncthreads();
#pragma unroll
        for (int i = 0; i < 8; i++) {
            Ks4[threadIdx.x + i * 128] = Kg[threadIdx.x + i * 128];
            Vs4[threadIdx.x + i * 128] = Vg[threadIdx.x + i * 128];
        }
        __syncthreads();

        for (int g = 0; g < 4; g++) {
            float s[16];
#pragma unroll
            for (int j = 0; j < 16; j++) {
                const float4* krow = (const float4*)(Ks + (g * 16 + j) * HDIM);
                float a0 = 0.f, a1 = 0.f, a2 = 0.f, a3 = 0.f;
#pragma unroll
                for (int d4 = 0; d4 < 16; d4++) {
                    float4 kv = krow[d4];
                    a0 = fmaf(q[d4 * 4 + 0], kv.x, a0);
                    a1 = fmaf(q[d4 * 4 + 1], kv.y, a1);
                    a2 = fmaf(q[d4 * 4 + 2], kv.z, a2);
                    a3 = fmaf(q[d4 * 4 + 3], kv.w, a3);
                }
                s[j] = (a0 + a1) + (a2 + a3);
            }
            float mt = m;
#pragma unroll
            for (int j = 0; j < 16; j++) mt = fmaxf(mt, s[j]);
            float corr = __expf(m - mt);
            m = mt;
            l *= corr;
#pragma unroll
            for (int d = 0; d < 64; d++) o[d] *= corr;
#pragma unroll
            for (int j = 0; j < 16; j++) {
                float p = __expf(s[j] - m);
                l += p;
                const float4* vrow = (const float4*)(Vs + (g * 16 + j) * HDIM);
#pragma unroll
                for (int d4 = 0; d4 < 16; d4++) {
                    float4 vv = vrow[d4];
                    o[d4 * 4 + 0] = fmaf(p, vv.x, o[d4 * 4 + 0]);
                    o[d4 * 4 + 1] = fmaf(p, vv.y, o[d4 * 4 + 1]);
                    o[d4 * 4 + 2] = fmaf(p, vv.z, o[d4 * 4 + 2]);
                    o[d4 * 4 + 3] = fmaf(p, vv.w, o[d4 * 4 + 3]);
                }
            }
        }
    }

    const float inv = 1.f / l;
    float* Oh = g_o + base + (size_t)qi * HDIM;
#pragma unroll
    for (int d4 = 0; d4 < 16; d4++) {
        float4 t;
        t.x = o[d4 * 4 + 0] * inv;
        t.y = o[d4 * 4 + 1] * inv;
        t.z = o[d4 * 4 + 2] * inv;
        t.w = o[d4 * 4 + 3] * inv;
        *(float4*)(Oh + d4 * 4) = t;
    }
}

// ---------------------------------------------------------------------------
extern "C" void kernel_launch(void* const* d_in, const int* in_sizes, int n_in,
                              void* d_out, int out_size) {
    const float* x  = (const float*)d_in[0];
    const float* wq = (const float*)d_in[1];
    const float* wk = (const float*)d_in[2];
    const float* wv = (const float*)d_in[3];
    const float* wo = (const float*)d_in[4];
    float* out = (float*)d_out;

    __nv_bfloat16 *xh, *xl, *wqh, *wql, *wkh, *wkl, *wvh, *wvl, *woh, *wol, *oh, *ol;
    cudaGetSymbolAddress((void**)&xh, g_xh);   cudaGetSymbolAddress((void**)&xl, g_xl);
    cudaGetSymbolAddress((void**)&wqh, g_wqh); cudaGetSymbolAddress((void**)&wql, g_wql);
    cudaGetSymbolAddress((void**)&wkh, g_wkh); cudaGetSymbolAddress((void**)&wkl, g_wkl);
    cudaGetSymbolAddress((void**)&wvh, g_wvh); cudaGetSymbolAddress((void**)&wvl, g_wvl);
    cudaGetSymbolAddress((void**)&woh, g_woh); cudaGetSymbolAddress((void**)&wol, g_wol);
    cudaGetSymbolAddress((void**)&oh, g_oh);   cudaGetSymbolAddress((void**)&ol, g_ol);
    float* o32;
    cudaGetSymbolAddress((void**)&o32, g_o);

    const int nx4 = MTOT * HIDDEN / 4;      // 1M float4
    const int nw4 = HIDDEN * HIDDEN / 4;    // 256K float4
    convert_split_kernel<<<(nx4 + 255) / 256, 256>>>(x,  xh,  xl,  nx4);
    convert_split_kernel<<<(nw4 + 255) / 256, 256>>>(wq, wqh, wql, nw4);
    convert_split_kernel<<<(nw4 + 255) / 256, 256>>>(wk, wkh, wkl, nw4);
    convert_split_kernel<<<(nw4 + 255) / 256, 256>>>(wv, wvh, wvl, nw4);
    convert_split_kernel<<<(nw4 + 255) / 256, 256>>>(wo, woh, wol, nw4);

    // QKV projections on tensor cores (mma.sync)
    qkv_gemm_mma_kernel<<<dim3(HIDDEN / 128, MTOT / 128, 3), 256>>>();

    // Attention
    attn_kernel<<<dim3(SEQ / 128, NBH), 128>>>();

    // Split attention output, then output projection on tensor cores
    convert_split_kernel<<<(nx4 + 255) / 256, 256>>>(o32, oh, ol, nx4);
    out_gemm_mma_kernel<<<dim3(HIDDEN / 128, MTOT / 128, 1), 256>>>(out);
}

// round 10
// speedup vs baseline: 2.7989x; 1.8511x over previous
#include <cuda_runtime.h>
#include <cuda_bf16.h>
#include <cstdint>
#include <math.h>

// Problem constants
#define BSZ     4
#define SEQ     1024
#define HIDDEN  1024
#define NHEADS  16
#define HDIM    64
#define MTOT    (BSZ*SEQ)          // 4096
#define NBH     (BSZ*NHEADS)       // 64

// ---------------------------------------------------------------------------
// Scratch (device globals; allocation is forbidden). All intermediates are
// bf16 hi/lo split pairs (x = hi + lo, ~16 mantissa bits).
// ---------------------------------------------------------------------------
__device__ __nv_bfloat16 g_xh[MTOT * HIDDEN];
__device__ __nv_bfloat16 g_xl[MTOT * HIDDEN];
__device__ __nv_bfloat16 g_qh[MTOT * HIDDEN];
__device__ __nv_bfloat16 g_ql[MTOT * HIDDEN];
__device__ __nv_bfloat16 g_kh[MTOT * HIDDEN];
__device__ __nv_bfloat16 g_kl[MTOT * HIDDEN];
__device__ __nv_bfloat16 g_vh[MTOT * HIDDEN];
__device__ __nv_bfloat16 g_vl[MTOT * HIDDEN];
__device__ __nv_bfloat16 g_oh[MTOT * HIDDEN];
__device__ __nv_bfloat16 g_ol[MTOT * HIDDEN];
__device__ __nv_bfloat16 g_wqh[HIDDEN * HIDDEN];
__device__ __nv_bfloat16 g_wql[HIDDEN * HIDDEN];
__device__ __nv_bfloat16 g_wkh[HIDDEN * HIDDEN];
__device__ __nv_bfloat16 g_wkl[HIDDEN * HIDDEN];
__device__ __nv_bfloat16 g_wvh[HIDDEN * HIDDEN];
__device__ __nv_bfloat16 g_wvl[HIDDEN * HIDDEN];
__device__ __nv_bfloat16 g_woh[HIDDEN * HIDDEN];
__device__ __nv_bfloat16 g_wol[HIDDEN * HIDDEN];

// ---------------------------------------------------------------------------
// Warp-level tensor helpers (baseline PTX: valid under compute_103)
// ---------------------------------------------------------------------------
__device__ __forceinline__ uint32_t smem_to_u32(const void* p) {
    uint32_t addr;
    asm("{ .reg .u64 t; cvta.to.shared.u64 t, %1; cvt.u32.u64 %0, t; }"
        : "=r"(addr) : "l"(p));
    return addr;
}

__device__ __forceinline__ void ldsm_x4(uint32_t addr, uint32_t* r) {
    asm volatile("ldmatrix.sync.aligned.m8n8.x4.shared.b16 {%0,%1,%2,%3}, [%4];"
        : "=r"(r[0]), "=r"(r[1]), "=r"(r[2]), "=r"(r[3]) : "r"(addr));
}

__device__ __forceinline__ void ldsm_x4_t(uint32_t addr, uint32_t* r) {
    asm volatile("ldmatrix.sync.aligned.m8n8.x4.trans.shared.b16 {%0,%1,%2,%3}, [%4];"
        : "=r"(r[0]), "=r"(r[1]), "=r"(r[2]), "=r"(r[3]) : "r"(addr));
}

__device__ __forceinline__ void mma_bf16(float* c, const uint32_t* a,
                                         uint32_t b0, uint32_t b1) {
    asm volatile(
        "mma.sync.aligned.m16n8k16.row.col.f32.bf16.bf16.f32 "
        "{%0,%1,%2,%3}, {%4,%5,%6,%7}, {%8,%9}, {%0,%1,%2,%3};"
        : "+f"(c[0]), "+f"(c[1]), "+f"(c[2]), "+f"(c[3])
        : "r"(a[0]), "r"(a[1]), "r"(a[2]), "r"(a[3]), "r"(b0), "r"(b1));
}

__device__ __forceinline__ void cp16(uint32_t dst, const void* src) {
    asm volatile("cp.async.cg.shared.global [%0], [%1], 16;"
        :: "r"(dst), "l"(src));
}
#define CP_COMMIT() asm volatile("cp.async.commit_group;")
#define CP_WAIT(N)  asm volatile("cp.async.wait_group %0;" :: "n"(N))

// split pack: (a,b) -> hi bf16x2 + lo bf16x2 residual
__device__ __forceinline__ void split2(float a, float b, uint32_t& h, uint32_t& l) {
    __nv_bfloat162 hv = __floats2bfloat162_rn(a, b);
    __nv_bfloat162 lv = __floats2bfloat162_rn(a - __bfloat162float(hv.x),
                                              b - __bfloat162float(hv.y));
    h = *(uint32_t*)&hv;
    l = *(uint32_t*)&lv;
}

// ---------------------------------------------------------------------------
// fp32 -> bf16 hi/lo split conversion
// ---------------------------------------------------------------------------
__global__ __launch_bounds__(256) void convert_split_kernel(
    const float* __restrict__ src,
    __nv_bfloat16* __restrict__ hi,
    __nv_bfloat16* __restrict__ lo, int n4) {
    int i = blockIdx.x * blockDim.x + threadIdx.x;
    if (i >= n4) return;
    float4 v = ((const float4*)src)[i];
    uint32_t h0, l0, h1, l1;
    split2(v.x, v.y, h0, l0);
    split2(v.z, v.w, h1, l1);
    ((uint32_t*)hi)[i * 2 + 0] = h0;
    ((uint32_t*)hi)[i * 2 + 1] = h1;
    ((uint32_t*)lo)[i * 2 + 0] = l0;
    ((uint32_t*)lo)[i * 2 + 1] = l1;
}

// ---------------------------------------------------------------------------
// mma.sync GEMM: C[4096,1024] = (Ah+Al)[M,K] * (Wh+Wl)[N,K]^T  (both K-major)
// CTA tile 128x128, BK=32, 256 threads (8 warps, warp tile 64x32).
// Epilogue: write bf16 hi/lo split (Ch/Cl) or fp32 (Cf).
// ---------------------------------------------------------------------------
#define NCHUNKS  (HIDDEN / 32)     // 32 K-chunks
#define TILE_B   10240             // 128 rows * 80 bytes

__device__ __forceinline__ void gemm_mma_body(
    const __nv_bfloat16* __restrict__ Ah, const __nv_bfloat16* __restrict__ Al,
    const __nv_bfloat16* __restrict__ Wh, const __nv_bfloat16* __restrict__ Wl,
    __nv_bfloat16* __restrict__ Ch, __nv_bfloat16* __restrict__ Cl,
    float* __restrict__ Cf) {
    __shared__ __align__(16) char sm[4 * TILE_B];   // sAh | sAl | sWh | sWl

    const int tid  = threadIdx.x;
    const int lane = tid & 31;
    const int wid  = tid >> 5;
    const int wm   = (wid >> 2) * 64;
    const int wn   = (wid & 3) * 32;
    const int blockM = blockIdx.y * 128;
    const int blockN = blockIdx.x * 128;
    const uint32_t sbase = smem_to_u32(sm);

    const int prow = tid >> 2;
    const int pc   = tid & 3;
    const uint4* gAh = (const uint4*)Ah;
    const uint4* gAl = (const uint4*)Al;
    const uint4* gWh = (const uint4*)Wh;
    const uint4* gWl = (const uint4*)Wl;
    const size_t gA0 = (size_t)(blockM + prow) * 128 + pc;
    const size_t gA1 = gA0 + (size_t)64 * 128;
    const size_t gW0 = (size_t)(blockN + prow) * 128 + pc;
    const size_t gW1 = gW0 + (size_t)64 * 128;
    const uint32_t s0 = prow * 80 + pc * 16;
    const uint32_t s1 = s0 + 64 * 80;

    const int r8 = lane & 7, sel = lane >> 3;
    const uint32_t a_lane = (uint32_t)((wm + r8 + (sel & 1) * 8) * 80 + (sel >> 1) * 16);
    const uint32_t b_lane = (uint32_t)((wn + (sel >> 1) * 8 + r8) * 80 + (sel & 1) * 16);

    float acc[4][4][4];
#pragma unroll
    for (int m = 0; m < 4; m++)
#pragma unroll
        for (int n = 0; n < 4; n++)
#pragma unroll
            for (int i = 0; i < 4; i++) acc[m][n][i] = 0.f;

    uint4 pf[8];
    pf[0] = gAh[gA0]; pf[1] = gAh[gA1];
    pf[2] = gAl[gA0]; pf[3] = gAl[gA1];
    pf[4] = gWh[gW0]; pf[5] = gWh[gW1];
    pf[6] = gWl[gW0]; pf[7] = gWl[gW1];

    for (int ch = 0; ch < NCHUNKS; ch++) {
        __syncthreads();
        *(uint4*)(sm + 0 * TILE_B + s0) = pf[0];
        *(uint4*)(sm + 0 * TILE_B + s1) = pf[1];
        *(uint4*)(sm + 1 * TILE_B + s0) = pf[2];
        *(uint4*)(sm + 1 * TILE_B + s1) = pf[3];
        *(uint4*)(sm + 2 * TILE_B + s0) = pf[4];
        *(uint4*)(sm + 2 * TILE_B + s1) = pf[5];
        *(uint4*)(sm + 3 * TILE_B + s0) = pf[6];
        *(uint4*)(sm + 3 * TILE_B + s1) = pf[7];
        __syncthreads();

        if (ch + 1 < NCHUNKS) {
            const size_t o = (size_t)(ch + 1) * 4;
            pf[0] = gAh[gA0 + o]; pf[1] = gAh[gA1 + o];
            pf[2] = gAl[gA0 + o]; pf[3] = gAl[gA1 + o];
            pf[4] = gWh[gW0 + o]; pf[5] = gWh[gW1 + o];
            pf[6] = gWl[gW0 + o]; pf[7] = gWl[gW1 + o];
        }

#pragma unroll
        for (int ks = 0; ks < 2; ks++) {
            uint32_t bh[8], bl[8];
            ldsm_x4(sbase + 2 * TILE_B + b_lane + ks * 32, bh);
            ldsm_x4(sbase + 2 * TILE_B + b_lane + 16 * 80 + ks * 32, bh + 4);
            ldsm_x4(sbase + 3 * TILE_B + b_lane + ks * 32, bl);
            ldsm_x4(sbase + 3 * TILE_B + b_lane + 16 * 80 + ks * 32, bl + 4);
#pragma unroll
            for (int m = 0; m < 4; m++) {
                uint32_t ah[4], al[4];
                ldsm_x4(sbase + 0 * TILE_B + a_lane + m * (16 * 80) + ks * 32, ah);
                ldsm_x4(sbase + 1 * TILE_B + a_lane + m * (16 * 80) + ks * 32, al);
#pragma unroll
                for (int n = 0; n < 4; n++) {
                    mma_bf16(acc[m][n], ah, bh[n * 2], bh[n * 2 + 1]);
                    mma_bf16(acc[m][n], ah, bl[n * 2], bl[n * 2 + 1]);
                    mma_bf16(acc[m][n], al, bh[n * 2], bh[n * 2 + 1]);
                }
            }
        }
    }

    const int cr = lane >> 2;
    const int cc = (lane & 3) * 2;
#pragma unroll
    for (int m = 0; m < 4; m++) {
#pragma unroll
        for (int n = 0; n < 4; n++) {
            const size_t row = (size_t)(blockM + wm + m * 16 + cr);
            const size_t col = (size_t)(blockN + wn + n * 8 + cc);
            if (Cf) {
                *(float2*)(Cf + row * HIDDEN + col) =
                    make_float2(acc[m][n][0], acc[m][n][1]);
                *(float2*)(Cf + (row + 8) * HIDDEN + col) =
                    make_float2(acc[m][n][2], acc[m][n][3]);
            } else {
                uint32_t h, l;
                split2(acc[m][n][0], acc[m][n][1], h, l);
                *(uint32_t*)(Ch + row * HIDDEN + col) = h;
                *(uint32_t*)(Cl + row * HIDDEN + col) = l;
                split2(acc[m][n][2], acc[m][n][3], h, l);
                *(uint32_t*)(Ch + (row + 8) * HIDDEN + col) = h;
                *(uint32_t*)(Cl + (row + 8) * HIDDEN + col) = l;
            }
        }
    }
}

__global__ __launch_bounds__(256) void qkv_gemm_mma_kernel() {
    const __nv_bfloat16* Wh = (blockIdx.z == 0) ? g_wqh : (blockIdx.z == 1) ? g_wkh : g_wvh;
    const __nv_bfloat16* Wl = (blockIdx.z == 0) ? g_wql : (blockIdx.z == 1) ? g_wkl : g_wvl;
    __nv_bfloat16* Ch = (blockIdx.z == 0) ? g_qh : (blockIdx.z == 1) ? g_kh : g_vh;
    __nv_bfloat16* Cl = (blockIdx.z == 0) ? g_ql : (blockIdx.z == 1) ? g_kl : g_vl;
    gemm_mma_body(g_xh, g_xl, Wh, Wl, Ch, Cl, nullptr);
}

__global__ __launch_bounds__(256) void out_gemm_mma_kernel(float* __restrict__ out) {
    gemm_mma_body(g_oh, g_ol, g_woh, g_wol, nullptr, nullptr, out);
}

// ---------------------------------------------------------------------------
// Tensor-core flash attention.
// CTA = 128 q-rows of one (b,h) chunk (contiguous 1024x64). 256 thr, 8 warps,
// warp = 16 q rows. Key blocks of 64, cp.async double-buffered K/V hi/lo.
// S = (Qh+Ql)(Kh+Kl)^T (3 MMAs), online softmax on fragments,
// O += (Ph+Pl)(Vh+Vl) (3 MMAs), V^T via ldmatrix.x4.trans.
// ---------------------------------------------------------------------------
#define ROWB     144               // 64 bf16 = 128B + 16B pad
#define BUF_B    (64 * ROWB)       // 9216 per buffer
#define STAGE_B  (4 * BUF_B)       // Kh|Kl|Vh|Vl = 36864
#define ATT_SMEM (2 * STAGE_B)     // 73728

__global__ __launch_bounds__(256) void attn_mma_kernel() {
    extern __shared__ __align__(16) char asmem[];
    const uint32_t sb = smem_to_u32(asmem);
    const int tid = threadIdx.x, lane = tid & 31, wid = tid >> 5;
    const int r8 = lane & 7, sel = lane >> 3;
    const int q0 = blockIdx.x * 128;
    const size_t base = (size_t)blockIdx.y * (SEQ * HDIM);

    const uint4* gQh = (const uint4*)(g_qh + base);
    const uint4* gQl = (const uint4*)(g_ql + base);
    const uint4* gKh = (const uint4*)(g_kh + base);
    const uint4* gKl = (const uint4*)(g_kl + base);
    const uint4* gVh = (const uint4*)(g_vh + base);
    const uint4* gVl = (const uint4*)(g_vl + base);

    // ---- stage Q (hi then lo) through smem, fragments -> registers ----
    const uint32_t a_lane = (uint32_t)((r8 + (sel & 1) * 8) * ROWB + (sel >> 1) * 16);
    const uint32_t qbase = sb + (uint32_t)(wid * 16) * ROWB + a_lane;
    uint32_t qh[4][4], ql[4][4];
    {
        const int sr = tid >> 3, c = tid & 7;
#pragma unroll
        for (int i = 0; i < 4; i++)
            *(uint4*)(asmem + (sr + i * 32) * ROWB + c * 16) =
                gQh[(size_t)(q0 + sr + i * 32) * 8 + c];
        __syncthreads();
#pragma unroll
        for (int kt = 0; kt < 4; kt++) ldsm_x4(qbase + kt * 32, qh[kt]);
        __syncthreads();
#pragma unroll
        for (int i = 0; i < 4; i++)
            *(uint4*)(asmem + (sr + i * 32) * ROWB + c * 16) =
                gQl[(size_t)(q0 + sr + i * 32) * 8 + c];
        __syncthreads();
#pragma unroll
        for (int kt = 0; kt < 4; kt++) ldsm_x4(qbase + kt * 32, ql[kt]);
        __syncthreads();
    }

    const uint32_t b_lane = (uint32_t)(((sel >> 1) * 8 + r8) * ROWB + (sel & 1) * 16);
    const uint32_t v_lane = (uint32_t)(((sel & 1) * 8 + r8) * ROWB + (sel >> 1) * 16);

    float accO[8][4];
#pragma unroll
    for (int n = 0; n < 8; n++)
#pragma unroll
        for (int i = 0; i < 4; i++) accO[n][i] = 0.f;
    float m0 = -1e30f, m1 = -1e30f, l0 = 0.f, l1 = 0.f;

    // cp.async stage loader: 2048 x 16B per stage, 8 per thread
    const int srr = tid >> 3, sc = tid & 7;
    auto stage_load = [&](int kb, int s) {
        const uint32_t d0 = sb + (uint32_t)s * STAGE_B;
#pragma unroll
        for (int i = 0; i < 8; i++) {
            const int buf = i >> 1;
            const int rr = srr + (i & 1) * 32;
            const uint4* src = (buf == 0 ? gKh : buf == 1 ? gKl : buf == 2 ? gVh : gVl)
                               + (size_t)(kb * 64 + rr) * 8 + sc;
            cp16(d0 + buf * BUF_B + rr * ROWB + sc * 16, src);
        }
    };

    stage_load(0, 0);
    CP_COMMIT();

    for (int kb = 0; kb < 16; kb++) {
        if (kb + 1 < 16) {
            stage_load(kb + 1, (kb + 1) & 1);
            CP_COMMIT();
            CP_WAIT(1);
        } else {
            CP_WAIT(0);
        }
        __syncthreads();

        const uint32_t Kh = sb + (uint32_t)(kb & 1) * STAGE_B;
        const uint32_t Kl = Kh + BUF_B;
        const uint32_t Vh = Kh + 2 * BUF_B;
        const uint32_t Vl = Kh + 3 * BUF_B;

        // ---- S = Q K^T ----
        float S[8][4];
#pragma unroll
        for (int ng = 0; ng < 4; ng++) {
#pragma unroll
            for (int i = 0; i < 4; i++) { S[2 * ng][i] = 0.f; S[2 * ng + 1][i] = 0.f; }
#pragma unroll
            for (int kt = 0; kt < 4; kt++) {
                uint32_t Bh4[4], Bl4[4];
                ldsm_x4(Kh + ng * (16 * ROWB) + kt * 32 + b_lane, Bh4);
                ldsm_x4(Kl + ng * (16 * ROWB) + kt * 32 + b_lane, Bl4);
                mma_bf16(S[2 * ng],     qh[kt], Bh4[0], Bh4[1]);
                mma_bf16(S[2 * ng],     qh[kt], Bl4[0], Bl4[1]);
                mma_bf16(S[2 * ng],     ql[kt], Bh4[0], Bh4[1]);
                mma_bf16(S[2 * ng + 1], qh[kt], Bh4[2], Bh4[3]);
                mma_bf16(S[2 * ng + 1], qh[kt], Bl4[2], Bl4[3]);
                mma_bf16(S[2 * ng + 1], ql[kt], Bh4[2], Bh4[3]);
            }
        }

        // ---- online softmax (scale 0.125 applied here, exact) ----
        float bm0 = -1e30f, bm1 = -1e30f;
#pragma unroll
        for (int nt = 0; nt < 8; nt++) {
            S[nt][0] *= 0.125f; S[nt][1] *= 0.125f;
            S[nt][2] *= 0.125f; S[nt][3] *= 0.125f;
            bm0 = fmaxf(bm0, fmaxf(S[nt][0], S[nt][1]));
            bm1 = fmaxf(bm1, fmaxf(S[nt][2], S[nt][3]));
        }
        bm0 = fmaxf(bm0, __shfl_xor_sync(0xffffffff, bm0, 1));
        bm0 = fmaxf(bm0, __shfl_xor_sync(0xffffffff, bm0, 2));
        bm1 = fmaxf(bm1, __shfl_xor_sync(0xffffffff, bm1, 1));
        bm1 = fmaxf(bm1, __shfl_xor_sync(0xffffffff, bm1, 2));
        const float nm0 = fmaxf(m0, bm0), nm1 = fmaxf(m1, bm1);
        const float c0 = __expf(m0 - nm0), c1 = __expf(m1 - nm1);
        m0 = nm0; m1 = nm1;
        l0 *= c0; l1 *= c1;
#pragma unroll
        for (int nt = 0; nt < 8; nt++) {
            accO[nt][0] *= c0; accO[nt][1] *= c0;
            accO[nt][2] *= c1; accO[nt][3] *= c1;
        }

        // ---- P = exp(S - m), split into hi/lo A-fragments ----
        uint32_t ah[4][4], al[4][4];
#pragma unroll
        for (int nt = 0; nt < 8; nt++) {
            const float p0 = __expf(S[nt][0] - m0);
            const float p1 = __expf(S[nt][1] - m0);
            const float p2 = __expf(S[nt][2] - m1);
            const float p3 = __expf(S[nt][3] - m1);
            l0 += p0 + p1; l1 += p2 + p3;
            const int kt = nt >> 1, hi = (nt & 1) * 2;
            split2(p0, p1, ah[kt][hi],     al[kt][hi]);
            split2(p2, p3, ah[kt][hi + 1], al[kt][hi + 1]);
        }

        // ---- O += P V ----
#pragma unroll
        for (int dgp = 0; dgp < 4; dgp++) {
#pragma unroll
            for (int kt = 0; kt < 4; kt++) {
                uint32_t Vh4[4], Vl4[4];
                ldsm_x4_t(Vh + kt * (16 * ROWB) + dgp * 32 + v_lane, Vh4);
                ldsm_x4_t(Vl + kt * (16 * ROWB) + dgp * 32 + v_lane, Vl4);
                mma_bf16(accO[2 * dgp],     ah[kt], Vh4[0], Vh4[1]);
                mma_bf16(accO[2 * dgp],     al[kt], Vh4[0], Vh4[1]);
                mma_bf16(accO[2 * dgp],     ah[kt], Vl4[0], Vl4[1]);
                mma_bf16(accO[2 * dgp + 1], ah[kt], Vh4[2], Vh4[3]);
                mma_bf16(accO[2 * dgp + 1], al[kt], Vh4[2], Vh4[3]);
                mma_bf16(accO[2 * dgp + 1], ah[kt], Vl4[2], Vl4[3]);
            }
        }
        __syncthreads();
    }

    // ---- finalize: reduce l across quad, normalize, split-write O ----
    l0 += __shfl_xor_sync(0xffffffff, l0, 1);
    l0 += __shfl_xor_sync(0xffffffff, l0, 2);
    l1 += __shfl_xor_sync(0xffffffff, l1, 1);
    l1 += __shfl_xor_sync(0xffffffff, l1, 2);
    const float inv0 = 1.f / l0, inv1 = 1.f / l1;

    const int row0 = q0 + wid * 16 + (lane >> 2);
    const int cc = (lane & 3) * 2;
#pragma unroll
    for (int nt = 0; nt < 8; nt++) {
        const int col = nt * 8 + cc;
        uint32_t h, l;
        split2(accO[nt][0] * inv0, accO[nt][1] * inv0, h, l);
        *(uint32_t*)(g_oh + base + (size_t)row0 * HDIM + col) = h;
        *(uint32_t*)(g_ol + base + (size_t)row0 * HDIM + col) = l;
        split2(accO[nt][2] * inv1, accO[nt][3] * inv1, h, l);
        *(uint32_t*)(g_oh + base + (size_t)(row0 + 8) * HDIM + col) = h;
        *(uint32_t*)(g_ol + base + (size_t)(row0 + 8) * HDIM + col) = l;
    }
}

// ---------------------------------------------------------------------------
extern "C" void kernel_launch(void* const* d_in, const int* in_sizes, int n_in,
                              void* d_out, int out_size) {
    const float* x  = (const float*)d_in[0];
    const float* wq = (const float*)d_in[1];
    const float* wk = (const float*)d_in[2];
    const float* wv = (const float*)d_in[3];
    const float* wo = (const float*)d_in[4];
    float* out = (float*)d_out;

    cudaFuncSetAttribute(attn_mma_kernel,
                         cudaFuncAttributeMaxDynamicSharedMemorySize, ATT_SMEM);

    __nv_bfloat16 *xh, *xl, *wqh, *wql, *wkh, *wkl, *wvh, *wvl, *woh, *wol;
    cudaGetSymbolAddress((void**)&xh, g_xh);   cudaGetSymbolAddress((void**)&xl, g_xl);
    cudaGetSymbolAddress((void**)&wqh, g_wqh); cudaGetSymbolAddress((void**)&wql, g_wql);
    cudaGetSymbolAddress((void**)&wkh, g_wkh); cudaGetSymbolAddress((void**)&wkl, g_wkl);
    cudaGetSymbolAddress((void**)&wvh, g_wvh); cudaGetSymbolAddress((void**)&wvl, g_wvl);
    cudaGetSymbolAddress((void**)&woh, g_woh); cudaGetSymbolAddress((void**)&wol, g_wol);

    const int nx4 = MTOT * HIDDEN / 4;      // 1M float4
    const int nw4 = HIDDEN * HIDDEN / 4;    // 256K float4
    convert_split_kernel<<<(nx4 + 255) / 256, 256>>>(x,  xh,  xl,  nx4);
    convert_split_kernel<<<(nw4 + 255) / 256, 256>>>(wq, wqh, wql, nw4);
    convert_split_kernel<<<(nw4 + 255) / 256, 256>>>(wk, wkh, wkl, nw4);
    convert_split_kernel<<<(nw4 + 255) / 256, 256>>>(wv, wvh, wvl, nw4);
    convert_split_kernel<<<(nw4 + 255) / 256, 256>>>(wo, woh, wol, nw4);

    // QKV projections (mma.sync, split bf16 epilogue)
    qkv_gemm_mma_kernel<<<dim3(HIDDEN / 128, MTOT / 128, 3), 256>>>();

    // Tensor-core flash attention (writes split bf16 O)
    attn_mma_kernel<<<dim3(SEQ / 128, NBH), 256, ATT_SMEM>>>();

    // Output projection (fp32 out)
    out_gemm_mma_kernel<<<dim3(HIDDEN / 128, MTOT / 128, 1), 256>>>(out);
}